// round 3
// baseline (speedup 1.0000x reference)
#include <cuda_runtime.h>

// Problem constants
#define B_   16
#define C_   512
#define N_   4096   // H*W tokens per batch
#define M_   2048   // memory rows
#define TQ   32     // tokens per CTA
#define MC   64     // memory rows per chunk
#define QP   516    // padded smem row stride (floats): 2064B; 4*QP*4 % 128 handled via 16-row striding
#define NCHUNK (M_ / MC)
#define NTHREADS 256

// smem layout (floats):
//   qs   [TQ][QP]
//   ks   [MC][QP]
//   Ssm  [TQ][MC]
//   Sp   [TQ][MC]   (k-split partials)
//   m_s  [TQ], l_s [TQ], sc_s [TQ]
#define SMEM_FLOATS (TQ*QP + MC*QP + 2*TQ*MC + 3*TQ)

__global__ __launch_bounds__(NTHREADS, 1)
void memattn_fused_f32(const float* __restrict__ feat,
                       const float* __restrict__ mem,
                       float* __restrict__ out)
{
    extern __shared__ float smem[];
    float* qs   = smem;                 // TQ*QP
    float* ks   = qs + TQ * QP;         // MC*QP
    float* Ssm  = ks + MC * QP;         // TQ*MC
    float* Sp   = Ssm + TQ * MC;        // TQ*MC
    float* m_s  = Sp + TQ * MC;         // TQ
    float* l_s  = m_s + TQ;             // TQ
    float* sc_s = l_s + TQ;             // TQ

    const int t  = threadIdx.x;
    const int b  = blockIdx.y;
    const int n0 = blockIdx.x * TQ;

    if (t < TQ) { m_s[t] = -3.0e38f; l_s[t] = 0.0f; }

    // ---- load Q tile: qs[tok][c] = feat[b, c, n0+tok] (coalesced over tok) ----
    const float* fbase = feat + (size_t)b * C_ * N_ + n0;
    #pragma unroll 4
    for (int idx = t; idx < TQ * C_; idx += NTHREADS) {
        int tok = idx & (TQ - 1);
        int c   = idx >> 5;           // TQ == 32
        qs[tok * QP + c] = fbase[(size_t)c * N_ + tok];
    }

    // GEMM1 thread mapping: 2-way k-split, 8 token-groups, 16 mrow-groups
    const int kid = t >> 7;                 // 0..1  -> k range [kid*256, +256)
    const int tg  = (t & 127) >> 4;         // 0..7  -> tokens tg*4 .. tg*4+3
    const int mg  = t & 15;                 // 0..15 -> mrows  mg, mg+16, mg+32, mg+48

    // GEMM2 thread mapping: 8 token-groups x 32 col-groups
    const int tokg2 = t >> 5;               // 0..7  -> tokens tokg2*4 .. +3
    const int colg  = t & 31;               // cols: colg*4 + 128*i + cc

    float O[4][16];                          // [token][i*4+cc] accumulators
    #pragma unroll
    for (int a = 0; a < 4; a++)
        #pragma unroll
        for (int c = 0; c < 16; c++) O[a][c] = 0.0f;

    for (int ch = 0; ch < NCHUNK; ch++) {
        __syncthreads();   // previous GEMM2 done reading ks/Ssm; q load done (ch==0)

        // ---- load K chunk (MC x C) into ks, rows padded to QP ----
        const float* mbase = mem + (size_t)(ch * MC) * C_;
        #pragma unroll 4
        for (int idx = t; idx < MC * (C_ / 4); idx += NTHREADS) {
            int row = idx >> 7;          // C_/4 == 128
            int c4  = idx & 127;
            float4 v = *(const float4*)(mbase + (size_t)row * C_ + c4 * 4);
            *(float4*)(ks + row * QP + c4 * 4) = v;
        }
        __syncthreads();

        // ---- GEMM1: S[32][64] = Q @ K^T (k-split x2) ----
        float acc[4][4];
        #pragma unroll
        for (int i = 0; i < 4; i++)
            #pragma unroll
            for (int j = 0; j < 4; j++) acc[i][j] = 0.0f;

        const int kbeg = kid * 256;
        #pragma unroll 2
        for (int k = kbeg; k < kbeg + 256; k += 4) {
            float4 qv[4], kv[4];
            #pragma unroll
            for (int i = 0; i < 4; i++)
                qv[i] = *(const float4*)(qs + (tg * 4 + i) * QP + k);
            #pragma unroll
            for (int j = 0; j < 4; j++)
                kv[j] = *(const float4*)(ks + (mg + 16 * j) * QP + k);
            #pragma unroll
            for (int i = 0; i < 4; i++)
                #pragma unroll
                for (int j = 0; j < 4; j++) {
                    acc[i][j] += qv[i].x * kv[j].x;
                    acc[i][j] += qv[i].y * kv[j].y;
                    acc[i][j] += qv[i].z * kv[j].z;
                    acc[i][j] += qv[i].w * kv[j].w;
                }
        }
        if (kid == 1) {
            #pragma unroll
            for (int i = 0; i < 4; i++)
                #pragma unroll
                for (int j = 0; j < 4; j++)
                    Sp[(tg * 4 + i) * MC + (mg + 16 * j)] = acc[i][j];
        }
        __syncthreads();
        if (kid == 0) {
            #pragma unroll
            for (int i = 0; i < 4; i++)
                #pragma unroll
                for (int j = 0; j < 4; j++) {
                    int off = (tg * 4 + i) * MC + (mg + 16 * j);
                    Ssm[off] = acc[i][j] + Sp[off];
                }
        }
        __syncthreads();

        // ---- online softmax update: 8 lanes per token row ----
        {
            int row = t >> 3;
            int g   = t & 7;
            float mx = -3.0e38f;
            #pragma unroll
            for (int j = g; j < MC; j += 8) mx = fmaxf(mx, Ssm[row * MC + j]);
            mx = fmaxf(mx, __shfl_xor_sync(0xffffffffu, mx, 4));
            mx = fmaxf(mx, __shfl_xor_sync(0xffffffffu, mx, 2));
            mx = fmaxf(mx, __shfl_xor_sync(0xffffffffu, mx, 1));
            float oldm = m_s[row];
            float newm = fmaxf(oldm, mx);
            float sum = 0.0f;
            #pragma unroll
            for (int j = g; j < MC; j += 8) {
                float p = __expf(Ssm[row * MC + j] - newm);
                Ssm[row * MC + j] = p;
                sum += p;
            }
            sum += __shfl_xor_sync(0xffffffffu, sum, 4);
            sum += __shfl_xor_sync(0xffffffffu, sum, 2);
            sum += __shfl_xor_sync(0xffffffffu, sum, 1);
            if (g == 0) {
                float sc = __expf(oldm - newm);   // 0 on first chunk (oldm=-3e38)
                sc_s[row] = sc;
                m_s[row]  = newm;
                l_s[row]  = l_s[row] * sc + sum;
            }
        }
        __syncthreads();

        // ---- GEMM2: O += P @ K  (rescale-then-accumulate) ----
        #pragma unroll
        for (int tt = 0; tt < 4; tt++) {
            float sc = sc_s[tokg2 * 4 + tt];
            #pragma unroll
            for (int c = 0; c < 16; c++) O[tt][c] *= sc;
        }
        #pragma unroll 2
        for (int j = 0; j < MC; j++) {
            float4 kv[4];
            #pragma unroll
            for (int i = 0; i < 4; i++)
                kv[i] = *(const float4*)(ks + j * QP + colg * 4 + 128 * i);
            float p[4];
            #pragma unroll
            for (int tt = 0; tt < 4; tt++)
                p[tt] = Ssm[(tokg2 * 4 + tt) * MC + j];
            #pragma unroll
            for (int tt = 0; tt < 4; tt++)
                #pragma unroll
                for (int i = 0; i < 4; i++) {
                    O[tt][i * 4 + 0] += p[tt] * kv[i].x;
                    O[tt][i * 4 + 1] += p[tt] * kv[i].y;
                    O[tt][i * 4 + 2] += p[tt] * kv[i].z;
                    O[tt][i * 4 + 3] += p[tt] * kv[i].w;
                }
        }
    }

    // ---- epilogue: normalize and write out[b, c, n0+tok] ----
    float rl[4];
    #pragma unroll
    for (int tt = 0; tt < 4; tt++) rl[tt] = 1.0f / l_s[tokg2 * 4 + tt];

    float* obase = out + (size_t)b * C_ * N_ + n0;
    #pragma unroll
    for (int i = 0; i < 4; i++)
        #pragma unroll
        for (int cc = 0; cc < 4; cc++) {
            int c = colg * 4 + 128 * i + cc;
            #pragma unroll
            for (int tt = 0; tt < 4; tt++)
                obase[(size_t)c * N_ + tokg2 * 4 + tt] = O[tt][i * 4 + cc] * rl[tt];
        }
}

extern "C" void kernel_launch(void* const* d_in, const int* in_sizes, int n_in,
                              void* d_out, int out_size)
{
    const float* feat = (const float*)d_in[0];   // [16, 512, 64, 64]
    const float* mem  = (const float*)d_in[1];   // [2048, 512]
    float* out        = (float*)d_out;           // [16, 512, 64, 64]
    (void)in_sizes; (void)n_in; (void)out_size;

    const int smem_bytes = SMEM_FLOATS * (int)sizeof(float);   // 214,912 B
    cudaFuncSetAttribute(memattn_fused_f32,
                         cudaFuncAttributeMaxDynamicSharedMemorySize, smem_bytes);

    dim3 grid(N_ / TQ, B_);   // 128 x 16
    memattn_fused_f32<<<grid, NTHREADS, smem_bytes>>>(feat, mem, out);
}

// round 4
// speedup vs baseline: 1.0534x; 1.0534x over previous
#include <cuda_runtime.h>

// Problem constants
#define B_   16
#define C_   512
#define N_   4096   // H*W tokens per batch
#define M_   2048   // memory rows
#define TQ   32     // tokens per CTA
#define MC   64     // memory rows per chunk
#define QP   516    // padded smem row stride (floats): 2064B; 4*QP*4 % 128 handled via 16-row striding
#define NCHUNK (M_ / MC)
#define NTHREADS 256

// smem layout (floats):
//   qs   [TQ][QP]
//   ks   [MC][QP]
//   Ssm  [TQ][MC]
//   Sp   [TQ][MC]   (k-split partials)
//   m_s  [TQ], l_s [TQ], sc_s [TQ]
#define SMEM_FLOATS (TQ*QP + MC*QP + 2*TQ*MC + 3*TQ)

__global__ __launch_bounds__(NTHREADS, 1)
void memattn_fused_f32(const float* __restrict__ feat,
                       const float* __restrict__ mem,
                       float* __restrict__ out)
{
    extern __shared__ float smem[];
    float* qs   = smem;                 // TQ*QP
    float* ks   = qs + TQ * QP;         // MC*QP
    float* Ssm  = ks + MC * QP;         // TQ*MC
    float* Sp   = Ssm + TQ * MC;        // TQ*MC
    float* m_s  = Sp + TQ * MC;         // TQ
    float* l_s  = m_s + TQ;             // TQ
    float* sc_s = l_s + TQ;             // TQ

    const int t  = threadIdx.x;
    const int b  = blockIdx.y;
    const int n0 = blockIdx.x * TQ;

    if (t < TQ) { m_s[t] = -3.0e38f; l_s[t] = 0.0f; }

    // ---- load Q tile: qs[tok][c] = feat[b, c, n0+tok] (coalesced over tok) ----
    const float* fbase = feat + (size_t)b * C_ * N_ + n0;
    #pragma unroll 4
    for (int idx = t; idx < TQ * C_; idx += NTHREADS) {
        int tok = idx & (TQ - 1);
        int c   = idx >> 5;           // TQ == 32
        qs[tok * QP + c] = fbase[(size_t)c * N_ + tok];
    }

    // GEMM1 thread mapping: 2-way k-split, 8 token-groups, 16 mrow-groups
    const int kid = t >> 7;                 // 0..1  -> k range [kid*256, +256)
    const int tg  = (t & 127) >> 4;         // 0..7  -> tokens tg*4 .. tg*4+3
    const int mg  = t & 15;                 // 0..15 -> mrows  mg, mg+16, mg+32, mg+48

    // GEMM2 thread mapping: 8 token-groups x 32 col-groups
    const int tokg2 = t >> 5;               // 0..7  -> tokens tokg2*4 .. +3
    const int colg  = t & 31;               // cols: colg*4 + 128*i + cc

    float O[4][16];                          // [token][i*4+cc] accumulators
    #pragma unroll
    for (int a = 0; a < 4; a++)
        #pragma unroll
        for (int c = 0; c < 16; c++) O[a][c] = 0.0f;

    for (int ch = 0; ch < NCHUNK; ch++) {
        __syncthreads();   // previous GEMM2 done reading ks/Ssm; q load done (ch==0)

        // ---- load K chunk (MC x C) into ks, rows padded to QP ----
        const float* mbase = mem + (size_t)(ch * MC) * C_;
        #pragma unroll 4
        for (int idx = t; idx < MC * (C_ / 4); idx += NTHREADS) {
            int row = idx >> 7;          // C_/4 == 128
            int c4  = idx & 127;
            float4 v = *(const float4*)(mbase + (size_t)row * C_ + c4 * 4);
            *(float4*)(ks + row * QP + c4 * 4) = v;
        }
        __syncthreads();

        // ---- GEMM1: S[32][64] = Q @ K^T (k-split x2) ----
        float acc[4][4];
        #pragma unroll
        for (int i = 0; i < 4; i++)
            #pragma unroll
            for (int j = 0; j < 4; j++) acc[i][j] = 0.0f;

        const int kbeg = kid * 256;
        #pragma unroll 2
        for (int k = kbeg; k < kbeg + 256; k += 4) {
            float4 qv[4], kv[4];
            #pragma unroll
            for (int i = 0; i < 4; i++)
                qv[i] = *(const float4*)(qs + (tg * 4 + i) * QP + k);
            #pragma unroll
            for (int j = 0; j < 4; j++)
                kv[j] = *(const float4*)(ks + (mg + 16 * j) * QP + k);
            #pragma unroll
            for (int i = 0; i < 4; i++)
                #pragma unroll
                for (int j = 0; j < 4; j++) {
                    acc[i][j] += qv[i].x * kv[j].x;
                    acc[i][j] += qv[i].y * kv[j].y;
                    acc[i][j] += qv[i].z * kv[j].z;
                    acc[i][j] += qv[i].w * kv[j].w;
                }
        }
        if (kid == 1) {
            #pragma unroll
            for (int i = 0; i < 4; i++)
                #pragma unroll
                for (int j = 0; j < 4; j++)
                    Sp[(tg * 4 + i) * MC + (mg + 16 * j)] = acc[i][j];
        }
        __syncthreads();
        if (kid == 0) {
            #pragma unroll
            for (int i = 0; i < 4; i++)
                #pragma unroll
                for (int j = 0; j < 4; j++) {
                    int off = (tg * 4 + i) * MC + (mg + 16 * j);
                    Ssm[off] = acc[i][j] + Sp[off];
                }
        }
        __syncthreads();

        // ---- online softmax update: 8 lanes per token row ----
        {
            int row = t >> 3;
            int g   = t & 7;
            float mx = -3.0e38f;
            #pragma unroll
            for (int j = g; j < MC; j += 8) mx = fmaxf(mx, Ssm[row * MC + j]);
            mx = fmaxf(mx, __shfl_xor_sync(0xffffffffu, mx, 4));
            mx = fmaxf(mx, __shfl_xor_sync(0xffffffffu, mx, 2));
            mx = fmaxf(mx, __shfl_xor_sync(0xffffffffu, mx, 1));
            float oldm = m_s[row];
            float newm = fmaxf(oldm, mx);
            float sum = 0.0f;
            #pragma unroll
            for (int j = g; j < MC; j += 8) {
                float p = __expf(Ssm[row * MC + j] - newm);
                Ssm[row * MC + j] = p;
                sum += p;
            }
            sum += __shfl_xor_sync(0xffffffffu, sum, 4);
            sum += __shfl_xor_sync(0xffffffffu, sum, 2);
            sum += __shfl_xor_sync(0xffffffffu, sum, 1);
            if (g == 0) {
                float sc = __expf(oldm - newm);   // 0 on first chunk (oldm=-3e38)
                sc_s[row] = sc;
                m_s[row]  = newm;
                l_s[row]  = l_s[row] * sc + sum;
            }
        }
        __syncthreads();

        // ---- GEMM2: O += P @ K  (rescale-then-accumulate) ----
        #pragma unroll
        for (int tt = 0; tt < 4; tt++) {
            float sc = sc_s[tokg2 * 4 + tt];
            #pragma unroll
            for (int c = 0; c < 16; c++) O[tt][c] *= sc;
        }
        #pragma unroll 2
        for (int j = 0; j < MC; j++) {
            float4 kv[4];
            #pragma unroll
            for (int i = 0; i < 4; i++)
                kv[i] = *(const float4*)(ks + j * QP + colg * 4 + 128 * i);
            float p[4];
            #pragma unroll
            for (int tt = 0; tt < 4; tt++)
                p[tt] = Ssm[(tokg2 * 4 + tt) * MC + j];
            #pragma unroll
            for (int tt = 0; tt < 4; tt++)
                #pragma unroll
                for (int i = 0; i < 4; i++) {
                    O[tt][i * 4 + 0] += p[tt] * kv[i].x;
                    O[tt][i * 4 + 1] += p[tt] * kv[i].y;
                    O[tt][i * 4 + 2] += p[tt] * kv[i].z;
                    O[tt][i * 4 + 3] += p[tt] * kv[i].w;
                }
        }
    }

    // ---- epilogue: normalize and write out[b, c, n0+tok] ----
    float rl[4];
    #pragma unroll
    for (int tt = 0; tt < 4; tt++) rl[tt] = 1.0f / l_s[tokg2 * 4 + tt];

    float* obase = out + (size_t)b * C_ * N_ + n0;
    #pragma unroll
    for (int i = 0; i < 4; i++)
        #pragma unroll
        for (int cc = 0; cc < 4; cc++) {
            int c = colg * 4 + 128 * i + cc;
            #pragma unroll
            for (int tt = 0; tt < 4; tt++)
                obase[(size_t)c * N_ + tokg2 * 4 + tt] = O[tt][i * 4 + cc] * rl[tt];
        }
}

extern "C" void kernel_launch(void* const* d_in, const int* in_sizes, int n_in,
                              void* d_out, int out_size)
{
    const float* feat = (const float*)d_in[0];   // [16, 512, 64, 64]
    const float* mem  = (const float*)d_in[1];   // [2048, 512]
    float* out        = (float*)d_out;           // [16, 512, 64, 64]
    (void)in_sizes; (void)n_in; (void)out_size;

    const int smem_bytes = SMEM_FLOATS * (int)sizeof(float);   // 214,912 B
    cudaFuncSetAttribute(memattn_fused_f32,
                         cudaFuncAttributeMaxDynamicSharedMemorySize, smem_bytes);

    dim3 grid(N_ / TQ, B_);   // 128 x 16
    memattn_fused_f32<<<grid, NTHREADS, smem_bytes>>>(feat, mem, out);
}

// round 5
// speedup vs baseline: 1.0535x; 1.0002x over previous
#include <cuda_runtime.h>

// Problem constants
#define B_   16
#define C_   512
#define N_   4096   // H*W tokens per batch
#define M_   2048   // memory rows
#define TQ   32     // tokens per CTA
#define MC   64     // memory rows per chunk
#define QP   516    // padded smem row stride (floats): 2064B; 4*QP*4 % 128 handled via 16-row striding
#define NCHUNK (M_ / MC)
#define NTHREADS 256

// smem layout (floats):
//   qs   [TQ][QP]
//   ks   [MC][QP]
//   Ssm  [TQ][MC]
//   Sp   [TQ][MC]   (k-split partials)
//   m_s  [TQ], l_s [TQ], sc_s [TQ]
#define SMEM_FLOATS (TQ*QP + MC*QP + 2*TQ*MC + 3*TQ)

__global__ __launch_bounds__(NTHREADS, 1)
void memattn_fused_f32(const float* __restrict__ feat,
                       const float* __restrict__ mem,
                       float* __restrict__ out)
{
    extern __shared__ float smem[];
    float* qs   = smem;                 // TQ*QP
    float* ks   = qs + TQ * QP;         // MC*QP
    float* Ssm  = ks + MC * QP;         // TQ*MC
    float* Sp   = Ssm + TQ * MC;        // TQ*MC
    float* m_s  = Sp + TQ * MC;         // TQ
    float* l_s  = m_s + TQ;             // TQ
    float* sc_s = l_s + TQ;             // TQ

    const int t  = threadIdx.x;
    const int b  = blockIdx.y;
    const int n0 = blockIdx.x * TQ;

    if (t < TQ) { m_s[t] = -3.0e38f; l_s[t] = 0.0f; }

    // ---- load Q tile: qs[tok][c] = feat[b, c, n0+tok] (coalesced over tok) ----
    const float* fbase = feat + (size_t)b * C_ * N_ + n0;
    #pragma unroll 4
    for (int idx = t; idx < TQ * C_; idx += NTHREADS) {
        int tok = idx & (TQ - 1);
        int c   = idx >> 5;           // TQ == 32
        qs[tok * QP + c] = fbase[(size_t)c * N_ + tok];
    }

    // GEMM1 thread mapping: 2-way k-split, 8 token-groups, 16 mrow-groups
    const int kid = t >> 7;                 // 0..1  -> k range [kid*256, +256)
    const int tg  = (t & 127) >> 4;         // 0..7  -> tokens tg*4 .. tg*4+3
    const int mg  = t & 15;                 // 0..15 -> mrows  mg, mg+16, mg+32, mg+48

    // GEMM2 thread mapping: 8 token-groups x 32 col-groups
    const int tokg2 = t >> 5;               // 0..7  -> tokens tokg2*4 .. +3
    const int colg  = t & 31;               // cols: colg*4 + 128*i + cc

    float O[4][16];                          // [token][i*4+cc] accumulators
    #pragma unroll
    for (int a = 0; a < 4; a++)
        #pragma unroll
        for (int c = 0; c < 16; c++) O[a][c] = 0.0f;

    for (int ch = 0; ch < NCHUNK; ch++) {
        __syncthreads();   // previous GEMM2 done reading ks/Ssm; q load done (ch==0)

        // ---- load K chunk (MC x C) into ks, rows padded to QP ----
        const float* mbase = mem + (size_t)(ch * MC) * C_;
        #pragma unroll 4
        for (int idx = t; idx < MC * (C_ / 4); idx += NTHREADS) {
            int row = idx >> 7;          // C_/4 == 128
            int c4  = idx & 127;
            float4 v = *(const float4*)(mbase + (size_t)row * C_ + c4 * 4);
            *(float4*)(ks + row * QP + c4 * 4) = v;
        }
        __syncthreads();

        // ---- GEMM1: S[32][64] = Q @ K^T (k-split x2) ----
        float acc[4][4];
        #pragma unroll
        for (int i = 0; i < 4; i++)
            #pragma unroll
            for (int j = 0; j < 4; j++) acc[i][j] = 0.0f;

        const int kbeg = kid * 256;
        #pragma unroll 2
        for (int k = kbeg; k < kbeg + 256; k += 4) {
            float4 qv[4], kv[4];
            #pragma unroll
            for (int i = 0; i < 4; i++)
                qv[i] = *(const float4*)(qs + (tg * 4 + i) * QP + k);
            #pragma unroll
            for (int j = 0; j < 4; j++)
                kv[j] = *(const float4*)(ks + (mg + 16 * j) * QP + k);
            #pragma unroll
            for (int i = 0; i < 4; i++)
                #pragma unroll
                for (int j = 0; j < 4; j++) {
                    acc[i][j] += qv[i].x * kv[j].x;
                    acc[i][j] += qv[i].y * kv[j].y;
                    acc[i][j] += qv[i].z * kv[j].z;
                    acc[i][j] += qv[i].w * kv[j].w;
                }
        }
        if (kid == 1) {
            #pragma unroll
            for (int i = 0; i < 4; i++)
                #pragma unroll
                for (int j = 0; j < 4; j++)
                    Sp[(tg * 4 + i) * MC + (mg + 16 * j)] = acc[i][j];
        }
        __syncthreads();
        if (kid == 0) {
            #pragma unroll
            for (int i = 0; i < 4; i++)
                #pragma unroll
                for (int j = 0; j < 4; j++) {
                    int off = (tg * 4 + i) * MC + (mg + 16 * j);
                    Ssm[off] = acc[i][j] + Sp[off];
                }
        }
        __syncthreads();

        // ---- online softmax update: 8 lanes per token row ----
        {
            int row = t >> 3;
            int g   = t & 7;
            float mx = -3.0e38f;
            #pragma unroll
            for (int j = g; j < MC; j += 8) mx = fmaxf(mx, Ssm[row * MC + j]);
            mx = fmaxf(mx, __shfl_xor_sync(0xffffffffu, mx, 4));
            mx = fmaxf(mx, __shfl_xor_sync(0xffffffffu, mx, 2));
            mx = fmaxf(mx, __shfl_xor_sync(0xffffffffu, mx, 1));
            float oldm = m_s[row];
            float newm = fmaxf(oldm, mx);
            float sum = 0.0f;
            #pragma unroll
            for (int j = g; j < MC; j += 8) {
                float p = __expf(Ssm[row * MC + j] - newm);
                Ssm[row * MC + j] = p;
                sum += p;
            }
            sum += __shfl_xor_sync(0xffffffffu, sum, 4);
            sum += __shfl_xor_sync(0xffffffffu, sum, 2);
            sum += __shfl_xor_sync(0xffffffffu, sum, 1);
            if (g == 0) {
                float sc = __expf(oldm - newm);   // 0 on first chunk (oldm=-3e38)
                sc_s[row] = sc;
                m_s[row]  = newm;
                l_s[row]  = l_s[row] * sc + sum;
            }
        }
        __syncthreads();

        // ---- GEMM2: O += P @ K  (rescale-then-accumulate) ----
        #pragma unroll
        for (int tt = 0; tt < 4; tt++) {
            float sc = sc_s[tokg2 * 4 + tt];
            #pragma unroll
            for (int c = 0; c < 16; c++) O[tt][c] *= sc;
        }
        #pragma unroll 2
        for (int j = 0; j < MC; j++) {
            float4 kv[4];
            #pragma unroll
            for (int i = 0; i < 4; i++)
                kv[i] = *(const float4*)(ks + j * QP + colg * 4 + 128 * i);
            float p[4];
            #pragma unroll
            for (int tt = 0; tt < 4; tt++)
                p[tt] = Ssm[(tokg2 * 4 + tt) * MC + j];
            #pragma unroll
            for (int tt = 0; tt < 4; tt++)
                #pragma unroll
                for (int i = 0; i < 4; i++) {
                    O[tt][i * 4 + 0] += p[tt] * kv[i].x;
                    O[tt][i * 4 + 1] += p[tt] * kv[i].y;
                    O[tt][i * 4 + 2] += p[tt] * kv[i].z;
                    O[tt][i * 4 + 3] += p[tt] * kv[i].w;
                }
        }
    }

    // ---- epilogue: normalize and write out[b, c, n0+tok] ----
    float rl[4];
    #pragma unroll
    for (int tt = 0; tt < 4; tt++) rl[tt] = 1.0f / l_s[tokg2 * 4 + tt];

    float* obase = out + (size_t)b * C_ * N_ + n0;
    #pragma unroll
    for (int i = 0; i < 4; i++)
        #pragma unroll
        for (int cc = 0; cc < 4; cc++) {
            int c = colg * 4 + 128 * i + cc;
            #pragma unroll
            for (int tt = 0; tt < 4; tt++)
                obase[(size_t)c * N_ + tokg2 * 4 + tt] = O[tt][i * 4 + cc] * rl[tt];
        }
}

extern "C" void kernel_launch(void* const* d_in, const int* in_sizes, int n_in,
                              void* d_out, int out_size)
{
    const float* feat = (const float*)d_in[0];   // [16, 512, 64, 64]
    const float* mem  = (const float*)d_in[1];   // [2048, 512]
    float* out        = (float*)d_out;           // [16, 512, 64, 64]
    (void)in_sizes; (void)n_in; (void)out_size;

    const int smem_bytes = SMEM_FLOATS * (int)sizeof(float);   // 214,912 B
    cudaFuncSetAttribute(memattn_fused_f32,
                         cudaFuncAttributeMaxDynamicSharedMemorySize, smem_bytes);

    dim3 grid(N_ / TQ, B_);   // 128 x 16
    memattn_fused_f32<<<grid, NTHREADS, smem_bytes>>>(feat, mem, out);
}

// round 6
// speedup vs baseline: 1.2157x; 1.1539x over previous
#include <cuda_runtime.h>

// Problem constants
#define B_   16
#define C_   512
#define N_   4096
#define M_   2048
#define TQ   32      // tokens per CTA
#define MC   64      // memory rows per chunk
#define QP   516     // padded smem row stride (floats) for qs/ks
#define STQ  36      // padded stride for transposed score tile St[MC][STQ]
#define NCHUNK (M_ / MC)
#define NTHREADS 256

// smem (floats): qs[TQ][QP] + ks[MC][QP] + St[MC][STQ] + Sp[MC][STQ] + m/l/sc[TQ each]
#define SMEM_FLOATS (TQ*QP + MC*QP + 2*MC*STQ + 3*TQ)

typedef unsigned long long ull;

__device__ __forceinline__ ull fma2(ull a, ull b, ull c) {
    ull d;
    asm("fma.rn.f32x2 %0, %1, %2, %3;" : "=l"(d) : "l"(a), "l"(b), "l"(c));
    return d;
}
__device__ __forceinline__ ull mul2(ull a, ull b) {
    ull d;
    asm("mul.rn.f32x2 %0, %1, %2;" : "=l"(d) : "l"(a), "l"(b));
    return d;
}
__device__ __forceinline__ ull pack2(float x, float y) {
    ull d;
    asm("mov.b64 %0, {%1, %2};" : "=l"(d) : "f"(x), "f"(y));
    return d;
}
__device__ __forceinline__ void unpack2(ull d, float& x, float& y) {
    asm("mov.b64 {%0, %1}, %2;" : "=f"(x), "=f"(y) : "l"(d));
}

__global__ __launch_bounds__(NTHREADS, 1)
void memattn_fused_f32x2(const float* __restrict__ feat,
                         const float* __restrict__ mem,
                         float* __restrict__ out)
{
    extern __shared__ float smem[];
    float* qs   = smem;                 // TQ*QP
    float* ks   = qs + TQ * QP;         // MC*QP
    float* St   = ks + MC * QP;         // MC*STQ  (scores, transposed: [mrow][tok])
    float* Sp   = St + MC * STQ;        // MC*STQ  (k-split partials, same layout)
    float* m_s  = Sp + MC * STQ;        // TQ
    float* l_s  = m_s + TQ;             // TQ
    float* sc_s = l_s + TQ;             // TQ

    const int t    = threadIdx.x;
    const int lane = t & 31;
    const int b    = blockIdx.y;
    const int n0   = blockIdx.x * TQ;

    if (t < TQ) { m_s[t] = -3.0e38f; l_s[t] = 0.0f; }

    // ---- load Q tile: qs[tok][c] = feat[b, c, n0+tok] (coalesced over tok) ----
    const float* fbase = feat + (size_t)b * C_ * N_ + n0;
    #pragma unroll 4
    for (int idx = t; idx < TQ * C_; idx += NTHREADS) {
        int tok = idx & (TQ - 1);
        int c   = idx >> 5;
        qs[tok * QP + c] = fbase[(size_t)c * N_ + tok];
    }

    // ---- GEMM1 mapping: 2-way k-split; within-warp tg spans 4, mg spans 8 ----
    const int kid   = t >> 7;                                   // 0..1
    const int warp5 = (t & 127) >> 5;                           // 0..3
    const int tg    = ((warp5 & 1) << 2) | ((lane >> 3) & 3);   // 0..7  -> tokens tg*4..+3
    const int mg    = ((warp5 >> 1) << 3) | (lane & 7);         // 0..15 -> mrows mg+16*j

    // ---- GEMM2 mapping: warp owns 64-col block; lane: tokg (8) x colg (4) ----
    const int tokg  = lane >> 2;                                // 0..7 -> tokens tokg*4..+3
    const int cbase = (t >> 5) * 64 + (lane & 3) * 4;           // cols cbase + 16*i + {0..3}

    ull O2[4][8];                                               // [token][col-pair]
    #pragma unroll
    for (int a = 0; a < 4; a++)
        #pragma unroll
        for (int c = 0; c < 8; c++) O2[a][c] = 0ull;

    for (int ch = 0; ch < NCHUNK; ch++) {
        __syncthreads();   // prev GEMM2 done with ks/St (and q-load on ch==0)

        // ---- load K chunk (MC x C) into ks ----
        const float* mbase = mem + (size_t)(ch * MC) * C_;
        #pragma unroll 4
        for (int idx = t; idx < MC * (C_ / 4); idx += NTHREADS) {
            int row = idx >> 7;
            int c4  = idx & 127;
            float4 v = *(const float4*)(mbase + (size_t)row * C_ + c4 * 4);
            *(float4*)(ks + row * QP + c4 * 4) = v;
        }
        __syncthreads();

        // ---- GEMM1: S = Q @ K^T, packed f32x2, 2-way k-split ----
        ull acc2[4][4];
        #pragma unroll
        for (int i = 0; i < 4; i++)
            #pragma unroll
            for (int j = 0; j < 4; j++) acc2[i][j] = 0ull;

        const int kbeg = kid * 256;
        #pragma unroll 2
        for (int k = kbeg; k < kbeg + 256; k += 4) {
            ulonglong2 qv[4], kv[4];
            #pragma unroll
            for (int i = 0; i < 4; i++)
                qv[i] = *(const ulonglong2*)(qs + (tg * 4 + i) * QP + k);
            #pragma unroll
            for (int j = 0; j < 4; j++)
                kv[j] = *(const ulonglong2*)(ks + (mg + 16 * j) * QP + k);
            #pragma unroll
            for (int i = 0; i < 4; i++)
                #pragma unroll
                for (int j = 0; j < 4; j++) {
                    acc2[i][j] = fma2(qv[i].x, kv[j].x, acc2[i][j]);
                    acc2[i][j] = fma2(qv[i].y, kv[j].y, acc2[i][j]);
                }
        }

        if (kid == 1) {
            #pragma unroll
            for (int i = 0; i < 4; i++)
                #pragma unroll
                for (int j = 0; j < 4; j++) {
                    float lo, hi; unpack2(acc2[i][j], lo, hi);
                    Sp[(mg + 16 * j) * STQ + tg * 4 + i] = lo + hi;
                }
        }
        __syncthreads();
        if (kid == 0) {
            #pragma unroll
            for (int i = 0; i < 4; i++)
                #pragma unroll
                for (int j = 0; j < 4; j++) {
                    float lo, hi; unpack2(acc2[i][j], lo, hi);
                    int off = (mg + 16 * j) * STQ + tg * 4 + i;
                    St[off] = lo + hi + Sp[off];
                }
        }
        __syncthreads();

        // ---- online softmax on St columns (per token), 8 lanes/token ----
        {
            int row = t >> 3;          // token
            int g   = t & 7;
            float mx = -3.0e38f;
            #pragma unroll
            for (int j = g; j < MC; j += 8) mx = fmaxf(mx, St[j * STQ + row]);
            mx = fmaxf(mx, __shfl_xor_sync(0xffffffffu, mx, 4));
            mx = fmaxf(mx, __shfl_xor_sync(0xffffffffu, mx, 2));
            mx = fmaxf(mx, __shfl_xor_sync(0xffffffffu, mx, 1));
            float oldm = m_s[row];
            float newm = fmaxf(oldm, mx);
            float sum = 0.0f;
            #pragma unroll
            for (int j = g; j < MC; j += 8) {
                float p = __expf(St[j * STQ + row] - newm);
                St[j * STQ + row] = p;
                sum += p;
            }
            sum += __shfl_xor_sync(0xffffffffu, sum, 4);
            sum += __shfl_xor_sync(0xffffffffu, sum, 2);
            sum += __shfl_xor_sync(0xffffffffu, sum, 1);
            if (g == 0) {
                float sc = __expf(oldm - newm);
                sc_s[row] = sc;
                m_s[row]  = newm;
                l_s[row]  = l_s[row] * sc + sum;
            }
        }
        __syncthreads();

        // ---- GEMM2: O += P @ K (packed f32x2, rescale-then-accumulate) ----
        #pragma unroll
        for (int tt = 0; tt < 4; tt++) {
            float sc = sc_s[tokg * 4 + tt];
            ull sc2 = pack2(sc, sc);
            #pragma unroll
            for (int c = 0; c < 8; c++) O2[tt][c] = mul2(O2[tt][c], sc2);
        }
        #pragma unroll 4
        for (int j = 0; j < MC; j++) {
            float4 pf = *(const float4*)(St + j * STQ + tokg * 4);
            ull p2[4];
            p2[0] = pack2(pf.x, pf.x);
            p2[1] = pack2(pf.y, pf.y);
            p2[2] = pack2(pf.z, pf.z);
            p2[3] = pack2(pf.w, pf.w);
            #pragma unroll
            for (int i = 0; i < 4; i++) {
                ulonglong2 kv = *(const ulonglong2*)(ks + j * QP + cbase + 16 * i);
                #pragma unroll
                for (int tt = 0; tt < 4; tt++) {
                    O2[tt][2 * i + 0] = fma2(p2[tt], kv.x, O2[tt][2 * i + 0]);
                    O2[tt][2 * i + 1] = fma2(p2[tt], kv.y, O2[tt][2 * i + 1]);
                }
            }
        }
    }

    // ---- epilogue: normalize, write out[b, c, n0+tok] ----
    float rl[4];
    #pragma unroll
    for (int tt = 0; tt < 4; tt++) rl[tt] = 1.0f / l_s[tokg * 4 + tt];

    float* obase = out + (size_t)b * C_ * N_ + n0;
    #pragma unroll
    for (int i = 0; i < 4; i++)
        #pragma unroll
        for (int h = 0; h < 2; h++) {
            int c0 = cbase + 16 * i + 2 * h;
            #pragma unroll
            for (int tt = 0; tt < 4; tt++) {
                float a, bb; unpack2(O2[tt][2 * i + h], a, bb);
                int tok = tokg * 4 + tt;
                obase[(size_t)(c0 + 0) * N_ + tok] = a  * rl[tt];
                obase[(size_t)(c0 + 1) * N_ + tok] = bb * rl[tt];
            }
        }
}

extern "C" void kernel_launch(void* const* d_in, const int* in_sizes, int n_in,
                              void* d_out, int out_size)
{
    const float* feat = (const float*)d_in[0];   // [16, 512, 64, 64]
    const float* mem  = (const float*)d_in[1];   // [2048, 512]
    float* out        = (float*)d_out;
    (void)in_sizes; (void)n_in; (void)out_size;

    const int smem_bytes = SMEM_FLOATS * (int)sizeof(float);   // ~217 KB
    cudaFuncSetAttribute(memattn_fused_f32x2,
                         cudaFuncAttributeMaxDynamicSharedMemorySize, smem_bytes);

    dim3 grid(N_ / TQ, B_);   // 128 x 16
    memattn_fused_f32x2<<<grid, NTHREADS, smem_bytes>>>(feat, mem, out);
}